// round 14
// baseline (speedup 1.0000x reference)
#include <cuda_runtime.h>
#include <cuda_bf16.h>
#include <cstdint>

#define NTOK   16384   // B*S
#define DMODEL 256
#define NHEADS 8
#define DHID   2048    // DMODEL*NHEADS

#if defined(__CUDA_ARCH_SPECIFIC__) || defined(__CUDA_ARCH_FAMILY_SPECIFIC__)
#define HAS_TC05 1
#else
#define HAS_TC05 0
#endif

typedef __nv_bfloat16 bf16;

// ---------------- device-global scratch (allocation-free) -------------------
__device__ float g_Q [(size_t)NTOK * DHID];
__device__ float g_Kp[(size_t)NTOK * DHID];
__device__ float g_Vp[(size_t)NTOK * DHID];

// Panel-major pre-swizzled bf16 2-split operands.
__device__ bf16 g_Aq[(size_t)8  * NTOK * 64];
__device__ bf16 g_Ak[(size_t)8  * NTOK * 64];
__device__ bf16 g_Av[(size_t)8  * NTOK * 64];
__device__ bf16 g_AX[(size_t)64 * NTOK * 64];
__device__ bf16 g_Bq[(size_t)8  * DHID * 64];
__device__ bf16 g_Bk[(size_t)8  * DHID * 64];
__device__ bf16 g_Bv[(size_t)8  * DHID * 64];
__device__ bf16 g_Bo[(size_t)64 * DMODEL * 64];

__device__ int g_mask_mode;   // 0=float32, 1=int32, 2=uint8/bool

// ---------------- small PTX helpers -----------------------------------------
__device__ __forceinline__ uint32_t smem_u32(const void* p) {
    uint32_t a;
    asm("{ .reg .u64 t; cvta.to.shared.u64 t, %1; cvt.u32.u64 %0, t; }"
        : "=r"(a) : "l"(p));
    return a;
}
__device__ __forceinline__ void cp16(uint32_t dst, const void* src) {
    asm volatile("cp.async.cg.shared.global [%0], [%1], 16;" :: "r"(dst), "l"(src));
}
__device__ __forceinline__ void cp_commit() {
    asm volatile("cp.async.commit_group;" ::: "memory");
}
template <int N> __device__ __forceinline__ void cp_wait() {
    asm volatile("cp.async.wait_group %0;" :: "n"(N) : "memory");
}
__device__ __forceinline__ void mbar_init(uint32_t a, uint32_t cnt) {
    asm volatile("mbarrier.init.shared.b64 [%0], %1;" :: "r"(a), "r"(cnt) : "memory");
}
__device__ __forceinline__ void mbar_arrive(uint32_t a) {
    asm volatile("mbarrier.arrive.shared.b64 _, [%0];" :: "r"(a) : "memory");
}
__device__ __forceinline__ void mbar_wait(uint32_t a, uint32_t ph) {
    asm volatile(
        "{\n\t.reg .pred P1;\n"
        "LW%=:\n\tmbarrier.try_wait.parity.acquire.cta.shared::cta.b64 P1, [%0], %1;\n"
        "\t@P1 bra LD%=;\n\tbra LW%=;\n"
        "LD%=:\n\t}"
        :: "r"(a), "r"(ph) : "memory");
}
__device__ __forceinline__ void bar_named(int id) {
    asm volatile("bar.sync %0, 128;" :: "r"(id) : "memory");
}

// ---- tcgen05 wrappers (arch-specific pass only) -----------------------------
__device__ __forceinline__ void tc_alloc(uint32_t slot, uint32_t ncols) {
#if HAS_TC05
    asm volatile("tcgen05.alloc.cta_group::1.sync.aligned.shared::cta.b32 [%0], %1;"
                 :: "r"(slot), "r"(ncols) : "memory");
#endif
}
__device__ __forceinline__ void tc_dealloc(uint32_t tmem, uint32_t ncols) {
#if HAS_TC05
    asm volatile("tcgen05.dealloc.cta_group::1.sync.aligned.b32 %0, %1;"
                 :: "r"(tmem), "r"(ncols));
#endif
}
__device__ __forceinline__ void tc_commit(uint32_t mbar) {
#if HAS_TC05
    asm volatile("tcgen05.commit.cta_group::1.mbarrier::arrive::one.shared::cluster.b64 [%0];"
                 :: "r"(mbar) : "memory");
#else
    mbar_arrive(mbar);
#endif
}
__device__ __forceinline__ void mma_bf16(uint32_t d, uint64_t ad, uint64_t bd,
                                         uint32_t idesc, uint32_t acc) {
#if HAS_TC05
    asm volatile(
        "{\n\t.reg .pred p;\n"
        "\tsetp.ne.u32 p, %4, 0;\n"
        "\ttcgen05.mma.cta_group::1.kind::f16 [%0], %1, %2, %3, p;\n\t}"
        :: "r"(d), "l"(ad), "l"(bd), "r"(idesc), "r"(acc) : "memory");
#endif
}
__device__ __forceinline__ void ldtm32(uint32_t* r, uint32_t a) {
#if HAS_TC05
    asm volatile(
        "tcgen05.ld.sync.aligned.32x32b.x32.b32 "
        "{%0, %1, %2, %3, %4, %5, %6, %7, %8, %9, %10, %11, %12, %13, %14, %15, "
        "%16, %17, %18, %19, %20, %21, %22, %23, %24, %25, %26, %27, %28, %29, %30, %31}, [%32];"
        : "=r"(r[0]), "=r"(r[1]), "=r"(r[2]), "=r"(r[3]), "=r"(r[4]), "=r"(r[5]),
          "=r"(r[6]), "=r"(r[7]), "=r"(r[8]), "=r"(r[9]), "=r"(r[10]), "=r"(r[11]),
          "=r"(r[12]), "=r"(r[13]), "=r"(r[14]), "=r"(r[15]), "=r"(r[16]), "=r"(r[17]),
          "=r"(r[18]), "=r"(r[19]), "=r"(r[20]), "=r"(r[21]), "=r"(r[22]), "=r"(r[23]),
          "=r"(r[24]), "=r"(r[25]), "=r"(r[26]), "=r"(r[27]), "=r"(r[28]), "=r"(r[29]),
          "=r"(r[30]), "=r"(r[31])
        : "r"(a));
#else
#pragma unroll
    for (int i = 0; i < 32; i++) r[i] = 0u;
#endif
}
__device__ __forceinline__ void tc_wait_ld() {
#if HAS_TC05
    asm volatile("tcgen05.wait::ld.sync.aligned;" ::: "memory");
#endif
}
__device__ __forceinline__ void tc_fence_after() {
#if HAS_TC05
    asm volatile("tcgen05.fence::after_thread_sync;" ::: "memory");
#endif
}
__device__ __forceinline__ void tc_fence_before() {
#if HAS_TC05
    asm volatile("tcgen05.fence::before_thread_sync;" ::: "memory");
#endif
}

// SW128 K-major SMEM descriptor
__device__ __forceinline__ uint64_t mkdesc(uint32_t addr) {
    const uint64_t BASE = (2ull << 61) | (1ull << 46) | (64ull << 32) | (1ull << 16);
    return BASE | ((uint64_t)(addr >> 4) & 0x3FFF);
}

#define IDESC_BF16 ((1u << 4) | (1u << 7) | (1u << 10) | (16u << 17) | (8u << 24))

struct GemmArgs {
    const bf16 *A, *B;
    const float* bias;
    float* C;
};
struct GemmArgs3 { GemmArgs g[3]; };

// ---------------- persistent QKV GEMM: M256 x N256 jobs ----------------------
// Producer warps 0-3: stage ring of 3 (cp.async identity loads, prefetch runs
// across job boundaries); tid0 issues MMAs into the single 512-col TMEM
// accumulator, gating job j's first MMA on drain-free(j-1).
// Consumer warps 4-7: per-job TMEM drain in 16KB chunks (LDTM + bias + SMEM
// transpose + coalesced STG), overlapped with the next job's loads.
#define PSTAGE   65536                    // A 32KB + B 32KB
#define PEPI     (4096 + 3 * PSTAGE)      // 200704
#define PQKV_SMEM (PEPI + 16384)          // 217088

__global__ void __launch_bounds__(256, 1) gemm_qkv_persist(GemmArgs3 args) {
    extern __shared__ __align__(1024) char smem[];
    const uint32_t sb = smem_u32(smem);
    const int tid = threadIdx.x;
    const int w = tid >> 5, lane = tid & 31;
    const int bx = blockIdx.x, gsz = gridDim.x;
    const uint32_t SD = sb + 16;    // 3 stage-MMA-done mbars
    const uint32_t JD = sb + 48;    // job-done mbar
    const uint32_t DF = sb + 56;    // drain-free mbar (128 arrivals)

    if (tid == 0) {
        for (int i = 0; i < 3; i++) mbar_init(SD + i * 8, 1);
        mbar_init(JD, 1);
        mbar_init(DF, 128);
    }
    if (w == 0) tc_alloc(sb, 512);
    __syncthreads();
    uint32_t tmem;
    asm("ld.shared.b32 %0, [%1];" : "=r"(tmem) : "r"(sb));

    const int NJOBS = 1536;   // 8 N x 64 M x 3 matrices
    const int nj = (NJOBS > bx) ? (NJOBS - bx + gsz - 1) / gsz : 0;
    const int G = nj * 8;

    if (tid < 128) {
        // ---------------- producers: warps 0-3 -------------------------------
        auto load_stage = [&](int g) {
            if (g < G) {
                const int jl = g >> 3, p = g & 7;
                const int J = bx + gsz * jl;
                const int nt = J & 7;
                const int r2 = J >> 3;
                const int mt = r2 & 63, z = r2 >> 6;
                const char* A = reinterpret_cast<const char*>(args.g[z].A)
                              + ((size_t)p * NTOK + (size_t)mt * 256) * 128;
                const char* B = reinterpret_cast<const char*>(args.g[z].B)
                              + ((size_t)p * DHID + (size_t)nt * 256) * 128;
                const uint32_t st = sb + 4096 + (g % 3) * PSTAGE;
                const int t16 = tid << 4;
#pragma unroll
                for (int i = 0; i < 16; i++)
                    cp16(st + t16 + (i << 11), A + t16 + (i << 11));
#pragma unroll
                for (int i = 0; i < 16; i++)
                    cp16(st + 32768 + t16 + (i << 11), B + t16 + (i << 11));
            }
            cp_commit();
        };

        load_stage(0);
        load_stage(1);

        for (int g = 0; g < G; g++) {
            cp_wait<1>();
            asm volatile("fence.proxy.async.shared::cta;" ::: "memory");
            bar_named(1);
            const int jl = g >> 3, p = g & 7;
            if (tid == 0) {
                if (p == 0 && jl >= 1) {
                    mbar_wait(DF, (jl - 1) & 1);
                    tc_fence_after();
                }
                const uint32_t st = sb + 4096 + (g % 3) * PSTAGE;
#pragma unroll
                for (int mh = 0; mh < 2; mh++) {
                    const uint64_t ad = mkdesc(st) + mh * 1024;
#pragma unroll
                    for (int nh = 0; nh < 2; nh++) {
                        const uint32_t dt = tmem + mh * 256 + nh * 128;
                        const uint64_t bd = mkdesc(st + 32768) + nh * 1024;
                        mma_bf16(dt, ad + 0, bd + 0, IDESC_BF16, (p > 0) ? 1u : 0u);
                        mma_bf16(dt, ad + 2, bd + 2, IDESC_BF16, 1u);   // b0*b0
                        mma_bf16(dt, ad + 0, bd + 4, IDESC_BF16, 1u);   // b0*b1
                        mma_bf16(dt, ad + 2, bd + 6, IDESC_BF16, 1u);
                        mma_bf16(dt, ad + 4, bd + 0, IDESC_BF16, 1u);   // b1*b0
                        mma_bf16(dt, ad + 6, bd + 2, IDESC_BF16, 1u);
                    }
                }
                tc_commit(SD + (g % 3) * 8);
                if (p == 7) tc_commit(JD);
            }
            if (g >= 1)
                mbar_wait(SD + ((g - 1) % 3) * 8, ((g - 1) / 3) & 1);
            load_stage(g + 2);
        }
    } else {
        // ---------------- consumers: warps 4-7 -------------------------------
        const int ctid = tid - 128;
        float4* eb = reinterpret_cast<float4*>(smem + PEPI);
        for (int jl = 0; jl < nj; jl++) {
            mbar_wait(JD, jl & 1);
            tc_fence_after();
            const int J = bx + gsz * jl;
            const int nt = J & 7;
            const int r2 = J >> 3;
            const int mt = r2 & 63, z = r2 >> 6;
            const float* bias = args.g[z].bias + nt * 256;
            float* C = args.g[z].C + (size_t)mt * 256 * DHID + (size_t)nt * 256;
            const int row = (w & 3) * 32 + lane;
#pragma unroll
            for (int mh = 0; mh < 2; mh++) {
#pragma unroll
                for (int cc = 0; cc < 8; cc++) {
                    uint32_t r[32];
                    ldtm32(r, tmem + mh * 256 + cc * 32);
                    tc_wait_ld();
#pragma unroll
                    for (int j = 0; j < 8; j++) {
                        float4 bv = *reinterpret_cast<const float4*>(
                            bias + cc * 32 + j * 4);
                        float4 v;
                        v.x = __uint_as_float(r[4 * j + 0]) + bv.x;
                        v.y = __uint_as_float(r[4 * j + 1]) + bv.y;
                        v.z = __uint_as_float(r[4 * j + 2]) + bv.z;
                        v.w = __uint_as_float(r[4 * j + 3]) + bv.w;
                        eb[row * 8 + (j ^ (row & 7))] = v;
                    }
                    bar_named(2);
#pragma unroll
                    for (int i = 0; i < 8; i++) {
                        const int idx = ctid + (i << 7);
                        const int r3 = idx >> 3, c4 = idx & 7;
                        const float4 v = eb[r3 * 8 + (c4 ^ (r3 & 7))];
                        *reinterpret_cast<float4*>(
                            C + (size_t)(mh * 128 + r3) * DHID + cc * 32 + c4 * 4) = v;
                    }
                    bar_named(2);
                }
            }
            tc_fence_before();
            mbar_arrive(DF);
        }
    }

    __syncthreads();
    if (w == 0) tc_dealloc(tmem, 512);
}

// ---------------- out-proj GEMM (round-8 proven, M128 x N256, 4 stages) ------
#define GEMM_SMEM 200704

template <int MTILE, int NSTAGE>
__global__ void __launch_bounds__(256, 1) gemm_ps(GemmArgs3 args, int K, int Ntot) {
    constexpr int ABYTES = MTILE * 128;
    constexpr int BBYTES = 256 * 128;
    constexpr int STAGE  = ABYTES + BBYTES;
    constexpr int TCOLS  = (MTILE / 128) * 256;
    extern __shared__ __align__(1024) char smem[];
    const GemmArgs a = args.g[blockIdx.z];
    const uint32_t sb = smem_u32(smem);
    const int tid = threadIdx.x;
    const int w = tid >> 5, lane = tid & 31;
    const int m0 = blockIdx.y * MTILE, n0 = blockIdx.x * 256;
    const int P = K >> 5;

    if (tid == 0)
        for (int i = 0; i < NSTAGE; i++) mbar_init(sb + 16 + i * 8, 1);
    if (w == 0) tc_alloc(sb, TCOLS);
    float* bias_s = reinterpret_cast<float*>(smem + 1024);
    bias_s[tid] = a.bias[n0 + tid];
    __syncthreads();
    uint32_t tmem;
    asm("ld.shared.b32 %0, [%1];" : "=r"(tmem) : "r"(sb));

    auto load_stage = [&](int p, int buf) {
        if (p < P) {
            const uint32_t st = sb + 4096 + buf * STAGE;
            const char* sA = reinterpret_cast<const char*>(a.A)
                           + ((size_t)p * NTOK + m0) * 128;
            const char* sB = reinterpret_cast<const char*>(a.B)
                           + ((size_t)p * (size_t)Ntot + n0) * 128;
            const int t16 = tid << 4;
#pragma unroll
            for (int j = 0; j < ABYTES / 4096; j++)
                cp16(st + t16 + (j << 12), sA + t16 + (j << 12));
#pragma unroll
            for (int j = 0; j < BBYTES / 4096; j++)
                cp16(st + ABYTES + t16 + (j << 12), sB + t16 + (j << 12));
        }
        cp_commit();
    };

    for (int s = 0; s < NSTAGE - 1; s++) load_stage(s, s);

    for (int p = 0; p < P; p++) {
        const int buf = p % NSTAGE;
        cp_wait<NSTAGE - 2>();
        asm volatile("fence.proxy.async.shared::cta;" ::: "memory");
        __syncthreads();
        if (tid == 0) {
            const uint32_t st = sb + 4096 + buf * STAGE;
            const uint64_t ad0 = mkdesc(st);
            const uint64_t bd0 = mkdesc(st + ABYTES);
#pragma unroll
            for (int mh = 0; mh < MTILE / 128; mh++) {
                const uint64_t ad = ad0 + mh * 1024;
#pragma unroll
                for (int nh = 0; nh < 2; nh++) {
                    const uint32_t dt = tmem + mh * 256 + nh * 128;
                    const uint64_t bd = bd0 + nh * 1024;
                    mma_bf16(dt, ad + 0, bd + 0, IDESC_BF16, (p == 0) ? 0u : 1u);
                    mma_bf16(dt, ad + 2, bd + 2, IDESC_BF16, 1u);
                    mma_bf16(dt, ad + 0, bd + 4, IDESC_BF16, 1u);
                    mma_bf16(dt, ad + 2, bd + 6, IDESC_BF16, 1u);
                    mma_bf16(dt, ad + 4, bd + 0, IDESC_BF16, 1u);
                    mma_bf16(dt, ad + 6, bd + 2, IDESC_BF16, 1u);
                }
            }
            tc_commit(sb + 16 + buf * 8);
        }
        if (p >= 1) {
            const int q = p - 1;
            mbar_wait(sb + 16 + (q % NSTAGE) * 8, (q / NSTAGE) & 1);
        }
        load_stage(p + NSTAGE - 1, (p + NSTAGE - 1) % NSTAGE);
    }
    {
        const int q = P - 1;
        mbar_wait(sb + 16 + (q % NSTAGE) * 8, (q / NSTAGE) & 1);
    }

    tc_fence_after();
    float4* eb = reinterpret_cast<float4*>(smem + 4096);
    const int sp = w & 3;
    const int cb0 = (w < 4) ? 0 : 128;
    const int mrow = sp * 32 + lane;
#pragma unroll
    for (int mh = 0; mh < MTILE / 128; mh++) {
#pragma unroll
        for (int cb = 0; cb < 4; cb++) {
            const int colbase = cb0 + cb * 32;
            uint32_t r[32];
            ldtm32(r, tmem + mh * 256 + colbase);
            tc_wait_ld();
#pragma unroll
            for (int j = 0; j < 8; j++) {
                float4 v;
                v.x = __uint_as_float(r[4 * j + 0]) + bias_s[colbase + 4 * j + 0];
                v.y = __uint_as_float(r[4 * j + 1]) + bias_s[colbase + 4 * j + 1];
                v.z = __uint_as_float(r[4 * j + 2]) + bias_s[colbase + 4 * j + 2];
                v.w = __uint_as_float(r[4 * j + 3]) + bias_s[colbase + 4 * j + 3];
                const int c4 = (colbase >> 2) + j;
                eb[mrow * 64 + (c4 ^ (mrow & 7))] = v;
            }
        }
        __syncthreads();
#pragma unroll
        for (int i = 0; i < 32; i++) {
            const int idx = tid + (i << 8);
            const int row = idx >> 6, c4 = idx & 63;
            const float4 v = eb[row * 64 + (c4 ^ (row & 7))];
            *reinterpret_cast<float4*>(
                a.C + (size_t)(m0 + mh * 128 + row) * Ntot + n0 + (c4 << 2)) = v;
        }
        __syncthreads();
    }
    if (w == 0) tc_dealloc(tmem, TCOLS);
}

// ---------------- bf16 2-split + panel-swizzle writers -----------------------
__device__ __forceinline__ void split2(float x, bf16& b0, bf16& b1) {
    b0 = __float2bfloat16(x);
    b1 = __float2bfloat16(x - __bfloat162float(b0));
}
__device__ __forceinline__ void store_split4(char* base, int row, int kk,
                                             const float4& x) {
    bf16 b0[4], b1[4];
    split2(x.x, b0[0], b1[0]);
    split2(x.y, b0[1], b1[1]);
    split2(x.z, b0[2], b1[2]);
    split2(x.w, b0[3], b1[3]);
    const int c  = kk >> 3;
    const int bo = (kk & 7) * 2;
    *reinterpret_cast<uint2*>(base + ((c ^ (row & 7)) << 4) + bo) =
        *reinterpret_cast<uint2*>(b0);
    *reinterpret_cast<uint2*>(base + (((c + 4) ^ (row & 7)) << 4) + bo) =
        *reinterpret_cast<uint2*>(b1);
}

__global__ void split_inputs(const float4* __restrict__ q, const float4* __restrict__ k,
                             const float4* __restrict__ v,
                             const unsigned char* __restrict__ mask) {
    if (blockIdx.x == 0 && blockIdx.y == 0 && threadIdx.x < 32) {
        int lane = threadIdx.x;
        int big = 0, nzoff = 0;
        for (int i = lane; i < 1024; i += 32) {
            unsigned char mv = mask[i];
            if (mv > 1) big = 1;
            if ((i & 3) != 0 && mv != 0) nzoff = 1;
        }
        big   = __any_sync(0xffffffffu, big);
        nzoff = __any_sync(0xffffffffu, nzoff);
        if (lane == 0) g_mask_mode = big ? 0 : (nzoff ? 2 : 1);
    }
    const int i = blockIdx.x * 256 + threadIdx.x;
    const float4* s;
    bf16* dst;
    if (blockIdx.y == 0)      { s = q; dst = g_Aq; }
    else if (blockIdx.y == 1) { s = k; dst = g_Ak; }
    else                      { s = v; dst = g_Av; }
    const int r = i >> 6, j0 = (i & 63) << 2;
    const int p = j0 >> 5, kk = j0 & 31;
    char* base = reinterpret_cast<char*>(dst) + (((size_t)p * NTOK + r) << 7);
    store_split4(base, r, kk, s[i]);
}

__global__ void wsplit(const float* __restrict__ Wq, const float* __restrict__ Wk,
                       const float* __restrict__ Wv, const float* __restrict__ Wo) {
    const int z = blockIdx.z;
    const float* W; bf16* T; int K_, N_;
    if (z == 0)      { W = Wq; T = g_Bq; K_ = DMODEL; N_ = DHID; }
    else if (z == 1) { W = Wk; T = g_Bk; K_ = DMODEL; N_ = DHID; }
    else if (z == 2) { W = Wv; T = g_Bv; K_ = DMODEL; N_ = DHID; }
    else             { W = Wo; T = g_Bo; K_ = DHID;  N_ = DMODEL; }
    const int bx = blockIdx.x * 32;
    const int by = blockIdx.y * 32;
    if (bx >= N_ || by >= K_) return;
    __shared__ float t[32][33];
    const int tx = threadIdx.x, ty = threadIdx.y;
#pragma unroll
    for (int i = 0; i < 4; i++)
        t[ty + i * 8][tx] = W[(size_t)(by + ty + i * 8) * N_ + bx + tx];
    __syncthreads();
#pragma unroll
    for (int i = 0; i < 4; i++) {
        const int n = bx + ty + i * 8;
        const int kx = by + tx;
        const float x = t[tx][ty + i * 8];
        bf16 b0, b1;
        split2(x, b0, b1);
        const int p = kx >> 5, kk = kx & 31;
        const int c = kk >> 3, bo = (kk & 7) * 2;
        char* base = reinterpret_cast<char*>(T) + (((size_t)p * N_ + n) << 7);
        *reinterpret_cast<bf16*>(base + ((c ^ (n & 7)) << 4) + bo) = b0;
        *reinterpret_cast<bf16*>(base + (((c + 4) ^ (n & 7)) << 4) + bo) = b1;
    }
}

// ---------------- warp-per-token attention, folded reduction (round 13) ------
__global__ void __launch_bounds__(384, 1) attn_warp(const void* __restrict__ maskp) {
    const int lane = threadIdx.x & 31;
    const int t = blockIdx.x * 12 + (threadIdx.x >> 5);
    if (t >= NTOK) return;

    const float4* qb = reinterpret_cast<const float4*>(g_Q  + (size_t)t * DHID);
    const float4* kb = reinterpret_cast<const float4*>(g_Kp + (size_t)t * DHID);
    const float4* vb = reinterpret_cast<const float4*>(g_Vp + (size_t)t * DHID);
    const unsigned FULL = 0xffffffffu;

    float4 q0[8], q1[8];
#pragma unroll
    for (int h = 0; h < 8; h++) {
        q0[h] = qb[h * 64 + lane * 2];
        q1[h] = qb[h * 64 + lane * 2 + 1];
    }

    float own_p[8];
#pragma unroll
    for (int g = 0; g < 8; g++) {
        const float4 k0 = kb[g * 64 + lane * 2];
        const float4 k1 = kb[g * 64 + lane * 2 + 1];
        float s[8];
#pragma unroll
        for (int h = 0; h < 8; h++)
            s[h] = q0[h].x * k0.x + q0[h].y * k0.y + q0[h].z * k0.z + q0[h].w * k0.w
                 + q1[h].x * k1.x + q1[h].y * k1.y + q1[h].z * k1.z + q1[h].w * k1.w;
        const bool b4 = (lane & 16) != 0;
        float a[4];
#pragma unroll
        for (int j = 0; j < 4; j++) {
            const float sel = b4 ? s[j] : s[j + 4];
            const float r = __shfl_xor_sync(FULL, sel, 16);
            a[j] = (b4 ? s[j + 4] : s[j]) + r;
        }
        const bool b3 = (lane & 8) != 0;
        float bb[2];
#pragma unroll
        for (int j = 0; j < 2; j++) {
            const float sel = b3 ? a[j] : a[j + 2];
            const float r = __shfl_xor_sync(FULL, sel, 8);
            bb[j] = (b3 ? a[j + 2] : a[j]) + r;
        }
        const bool b2 = (lane & 4) != 0;
        {
            const float sel = b2 ? bb[0] : bb[1];
            const float r = __shfl_xor_sync(FULL, sel, 4);
            float c = (b2 ? bb[1] : bb[0]) + r;
            c += __shfl_xor_sync(FULL, c, 2);
            c += __shfl_xor_sync(FULL, c, 1);
            own_p[g] = c * 0.0625f;
        }
    }

    bool mv;
    {
        int mode = g_mask_mode;
        if (mode == 0)      mv = reinterpret_cast<const float*>(maskp)[t] != 0.0f;
        else if (mode == 1) mv = reinterpret_cast<const int*>(maskp)[t] != 0;
        else                mv = reinterpret_cast<const unsigned char*>(maskp)[t] != 0;
    }
    {
        float mx = -3.4e38f;
#pragma unroll
        for (int g = 0; g < 8; g++) {
            own_p[g] = mv ? own_p[g] : -1.0e9f;
            mx = fmaxf(mx, own_p[g]);
        }
        float sum = 0.f;
#pragma unroll
        for (int g = 0; g < 8; g++) { own_p[g] = expf(own_p[g] - mx); sum += own_p[g]; }
        const float inv = 1.0f / sum;
#pragma unroll
        for (int g = 0; g < 8; g++) own_p[g] *= inv;
    }

    float4 x0[8], x1[8];
#pragma unroll
    for (int h = 0; h < 8; h++) {
        x0[h] = make_float4(0.f, 0.f, 0.f, 0.f);
        x1[h] = make_float4(0.f, 0.f, 0.f, 0.f);
    }
#pragma unroll
    for (int g = 0; g < 8; g++) {
        const float4 v0 = vb[g * 64 + lane * 2];
        const float4 v1 = vb[g * 64 + lane * 2 + 1];
#pragma unroll
        for (int h = 0; h < 8; h++) {
            const float pg = __shfl_sync(FULL, own_p[g], h << 2);
            x0[h].x += pg * v0.x; x0[h].y += pg * v0.y;
            x0[h].z += pg * v0.z; x0[h].w += pg * v0.w;
            x1[h].x += pg * v1.x; x1[h].y += pg * v1.y;
            x1[h].z += pg * v1.z; x1[h].w += pg * v1.w;
        }
    }

    const int b = t >> 11, sIdx = t & 2047;
    const int kidx = (sIdx & 7) * 256 + lane * 8;
    const int pp = kidx >> 5, c = (kidx & 31) >> 3;
#pragma unroll
    for (int h = 0; h < 8; h++) {
        const int ar = b * 2048 + h * 256 + (sIdx >> 3);
        char* base = reinterpret_cast<char*>(g_AX) + (((size_t)pp * NTOK + ar) << 7);
        bf16 b0[8], b1[8];
        split2(x0[h].x, b0[0], b1[0]); split2(x0[h].y, b0[1], b1[1]);
        split2(x0[h].z, b0[2], b1[2]); split2(x0[h].w, b0[3], b1[3]);
        split2(x1[h].x, b0[4], b1[4]); split2(x1[h].y, b0[5], b1[5]);
        split2(x1[h].z, b0[6], b1[6]); split2(x1[h].w, b0[7], b1[7]);
        *reinterpret_cast<uint4*>(base + ((c ^ (ar & 7)) << 4)) =
            *reinterpret_cast<uint4*>(b0);
        *reinterpret_cast<uint4*>(base + (((c + 4) ^ (ar & 7)) << 4)) =
            *reinterpret_cast<uint4*>(b1);
    }
}

// ---------------- launch ------------------------------------------------------
extern "C" void kernel_launch(void* const* d_in, const int* in_sizes, int n_in,
                              void* d_out, int out_size) {
    const float* query = (const float*)d_in[0];
    const float* key   = (const float*)d_in[1];
    const float* value = (const float*)d_in[2];
    const void*  mask  = d_in[3];
    const float* Wq = (const float*)d_in[4];
    const float* bq = (const float*)d_in[5];
    const float* Wk = (const float*)d_in[6];
    const float* bk = (const float*)d_in[7];
    const float* Wv = (const float*)d_in[8];
    const float* bv = (const float*)d_in[9];
    const float* Wo = (const float*)d_in[10];
    const float* bo = (const float*)d_in[11];
    float* out = (float*)d_out;

    cudaFuncSetAttribute(gemm_qkv_persist,
                         cudaFuncAttributeMaxDynamicSharedMemorySize, PQKV_SMEM);
    cudaFuncSetAttribute(gemm_ps<128, 4>,
                         cudaFuncAttributeMaxDynamicSharedMemorySize, GEMM_SMEM);

    split_inputs<<<dim3((NTOK * DMODEL / 4) / 256, 3), 256>>>(
        (const float4*)query, (const float4*)key, (const float4*)value,
        (const unsigned char*)mask);
    wsplit<<<dim3(64, 64, 4), dim3(32, 8)>>>(Wq, Wk, Wv, Wo);

    bf16 *Aq, *Ak, *Av, *AX, *Bq, *Bk, *Bv, *Bo;
    float *Qp, *Kp, *Vp;
    cudaGetSymbolAddress((void**)&Aq, g_Aq);
    cudaGetSymbolAddress((void**)&Ak, g_Ak);
    cudaGetSymbolAddress((void**)&Av, g_Av);
    cudaGetSymbolAddress((void**)&AX, g_AX);
    cudaGetSymbolAddress((void**)&Bq, g_Bq);
    cudaGetSymbolAddress((void**)&Bk, g_Bk);
    cudaGetSymbolAddress((void**)&Bv, g_Bv);
    cudaGetSymbolAddress((void**)&Bo, g_Bo);
    cudaGetSymbolAddress((void**)&Qp, g_Q);
    cudaGetSymbolAddress((void**)&Kp, g_Kp);
    cudaGetSymbolAddress((void**)&Vp, g_Vp);

    // merged Q/K/V projections: persistent M256xN256 jobs over 148 CTAs
    GemmArgs3 qkv;
    qkv.g[0] = { Aq, Bq, bq, Qp };
    qkv.g[1] = { Ak, Bk, bk, Kp };
    qkv.g[2] = { Av, Bv, bv, Vp };
    gemm_qkv_persist<<<148, 256, PQKV_SMEM>>>(qkv);

    // warp-per-token attention: 12 warps/CTA
    attn_warp<<<(NTOK + 11) / 12, 384>>>(mask);

    // output projection: M=128 tiles, grid (1, 128)
    GemmArgs3 oarg;
    oarg.g[0] = { AX, Bo, bo, out };
    oarg.g[1] = oarg.g[0];
    oarg.g[2] = oarg.g[0];
    gemm_ps<128, 4><<<dim3(DMODEL / 256, NTOK / 128, 1), 256, GEMM_SMEM>>>(
        oarg, DHID, DMODEL);
}

// round 15
// speedup vs baseline: 1.3451x; 1.3451x over previous
#include <cuda_runtime.h>
#include <cuda_bf16.h>
#include <cstdint>

#define NTOK   16384   // B*S
#define DMODEL 256
#define NHEADS 8
#define DHID   2048    // DMODEL*NHEADS

#if defined(__CUDA_ARCH_SPECIFIC__) || defined(__CUDA_ARCH_FAMILY_SPECIFIC__)
#define HAS_TC05 1
#else
#define HAS_TC05 0
#endif

typedef __nv_bfloat16 bf16;

// ---------------- device-global scratch (allocation-free) -------------------
__device__ float g_Q [(size_t)NTOK * DHID];
__device__ float g_Kp[(size_t)NTOK * DHID];
__device__ float g_Vp[(size_t)NTOK * DHID];
__device__ float g_part[2][(size_t)NTOK * DMODEL];   // out-proj split-K partials
__device__ float g_zero[256];                        // zero bias (never written)

// Panel-major pre-swizzled bf16 2-split operands.
// arr[(p * ROWS + row) * 64 .. +64) bf16 = one 128B SW128 row
// [b0 k(32p..32p+31) | b1 same], chunk c stored at byte ((c ^ (row&7))<<4).
__device__ bf16 g_Aq[(size_t)8  * NTOK * 64];
__device__ bf16 g_Ak[(size_t)8  * NTOK * 64];
__device__ bf16 g_Av[(size_t)8  * NTOK * 64];
__device__ bf16 g_AX[(size_t)64 * NTOK * 64];
__device__ bf16 g_Bq[(size_t)8  * DHID * 64];
__device__ bf16 g_Bk[(size_t)8  * DHID * 64];
__device__ bf16 g_Bv[(size_t)8  * DHID * 64];
__device__ bf16 g_Bo[(size_t)64 * DMODEL * 64];

__device__ int g_mask_mode;   // 0=float32, 1=int32, 2=uint8/bool

// ---------------- small PTX helpers -----------------------------------------
__device__ __forceinline__ uint32_t smem_u32(const void* p) {
    uint32_t a;
    asm("{ .reg .u64 t; cvta.to.shared.u64 t, %1; cvt.u32.u64 %0, t; }"
        : "=r"(a) : "l"(p));
    return a;
}
__device__ __forceinline__ void cp16(uint32_t dst, const void* src) {
    asm volatile("cp.async.cg.shared.global [%0], [%1], 16;" :: "r"(dst), "l"(src));
}
__device__ __forceinline__ void cp_commit() {
    asm volatile("cp.async.commit_group;" ::: "memory");
}
template <int N> __device__ __forceinline__ void cp_wait() {
    asm volatile("cp.async.wait_group %0;" :: "n"(N) : "memory");
}
__device__ __forceinline__ void mbar_init(uint32_t a, uint32_t cnt) {
    asm volatile("mbarrier.init.shared.b64 [%0], %1;" :: "r"(a), "r"(cnt) : "memory");
}
__device__ __forceinline__ void mbar_wait(uint32_t a, uint32_t ph) {
    asm volatile(
        "{\n\t.reg .pred P1;\n"
        "LW%=:\n\tmbarrier.try_wait.parity.acquire.cta.shared::cta.b64 P1, [%0], %1;\n"
        "\t@P1 bra LD%=;\n\tbra LW%=;\n"
        "LD%=:\n\t}"
        :: "r"(a), "r"(ph) : "memory");
}

// ---- tcgen05 wrappers (arch-specific pass only) -----------------------------
__device__ __forceinline__ void tc_alloc(uint32_t slot, uint32_t ncols) {
#if HAS_TC05
    asm volatile("tcgen05.alloc.cta_group::1.sync.aligned.shared::cta.b32 [%0], %1;"
                 :: "r"(slot), "r"(ncols) : "memory");
#endif
}
__device__ __forceinline__ void tc_dealloc(uint32_t tmem, uint32_t ncols) {
#if HAS_TC05
    asm volatile("tcgen05.dealloc.cta_group::1.sync.aligned.b32 %0, %1;"
                 :: "r"(tmem), "r"(ncols));
#endif
}
__device__ __forceinline__ void tc_commit(uint32_t mbar) {
#if HAS_TC05
    asm volatile("tcgen05.commit.cta_group::1.mbarrier::arrive::one.shared::cluster.b64 [%0];"
                 :: "r"(mbar) : "memory");
#else
    asm volatile("mbarrier.arrive.shared.b64 _, [%0];" :: "r"(mbar) : "memory");
#endif
}
__device__ __forceinline__ void mma_bf16(uint32_t d, uint64_t ad, uint64_t bd,
                                         uint32_t idesc, uint32_t acc) {
#if HAS_TC05
    asm volatile(
        "{\n\t.reg .pred p;\n"
        "\tsetp.ne.u32 p, %4, 0;\n"
        "\ttcgen05.mma.cta_group::1.kind::f16 [%0], %1, %2, %3, p;\n\t}"
        :: "r"(d), "l"(ad), "l"(bd), "r"(idesc), "r"(acc) : "memory");
#endif
}
__device__ __forceinline__ void ldtm32(uint32_t* r, uint32_t a) {
#if HAS_TC05
    asm volatile(
        "tcgen05.ld.sync.aligned.32x32b.x32.b32 "
        "{%0, %1, %2, %3, %4, %5, %6, %7, %8, %9, %10, %11, %12, %13, %14, %15, "
        "%16, %17, %18, %19, %20, %21, %22, %23, %24, %25, %26, %27, %28, %29, %30, %31}, [%32];"
        : "=r"(r[0]), "=r"(r[1]), "=r"(r[2]), "=r"(r[3]), "=r"(r[4]), "=r"(r[5]),
          "=r"(r[6]), "=r"(r[7]), "=r"(r[8]), "=r"(r[9]), "=r"(r[10]), "=r"(r[11]),
          "=r"(r[12]), "=r"(r[13]), "=r"(r[14]), "=r"(r[15]), "=r"(r[16]), "=r"(r[17]),
          "=r"(r[18]), "=r"(r[19]), "=r"(r[20]), "=r"(r[21]), "=r"(r[22]), "=r"(r[23]),
          "=r"(r[24]), "=r"(r[25]), "=r"(r[26]), "=r"(r[27]), "=r"(r[28]), "=r"(r[29]),
          "=r"(r[30]), "=r"(r[31])
        : "r"(a));
#else
#pragma unroll
    for (int i = 0; i < 32; i++) r[i] = 0u;
#endif
}
__device__ __forceinline__ void tc_wait_ld() {
#if HAS_TC05
    asm volatile("tcgen05.wait::ld.sync.aligned;" ::: "memory");
#endif
}
__device__ __forceinline__ void tc_fence_after() {
#if HAS_TC05
    asm volatile("tcgen05.fence::after_thread_sync;" ::: "memory");
#endif
}

// SW128 K-major SMEM descriptor (LBO=1, SBO=64, version=1, layout=SW128)
__device__ __forceinline__ uint64_t mkdesc(uint32_t addr) {
    const uint64_t BASE = (2ull << 61) | (1ull << 46) | (64ull << 32) | (1ull << 16);
    return BASE | ((uint64_t)(addr >> 4) & 0x3FFF);
}

// idesc kind::f16: cF32(bit4), aBF16(bit7), bBF16(bit10), N=128 (16<<17), M=128 (8<<24)
#define IDESC_BF16 ((1u << 4) | (1u << 7) | (1u << 10) | (16u << 17) | (8u << 24))

// ---------------- GEMM: pre-swizzled panels, identity cp.async ---------------
struct GemmArgs {
    const bf16 *A, *B;
    const float* bias;
    float* C;
};
struct GemmArgs3 { GemmArgs g[3]; };

#define GEMM_SMEM 200704   // 4096 + 3*64KB

template <int MTILE, int NSTAGE>
__global__ void __launch_bounds__(256, 1) gemm_ps(GemmArgs3 args, int K, int Ntot) {
    constexpr int ABYTES = MTILE * 128;
    constexpr int BBYTES = 256 * 128;
    constexpr int STAGE  = ABYTES + BBYTES;
    constexpr int TCOLS  = (MTILE / 128) * 256;
    extern __shared__ __align__(1024) char smem[];
    const GemmArgs a = args.g[blockIdx.z];
    const uint32_t sb = smem_u32(smem);
    const int tid = threadIdx.x;
    const int w = tid >> 5, lane = tid & 31;
    const int m0 = blockIdx.y * MTILE, n0 = blockIdx.x * 256;
    const int P = K >> 5;

    if (tid == 0)
        for (int i = 0; i < NSTAGE; i++) mbar_init(sb + 16 + i * 8, 1);
    if (w == 0) tc_alloc(sb, TCOLS);
    float* bias_s = reinterpret_cast<float*>(smem + 1024);
    bias_s[tid] = a.bias[n0 + tid];
    __syncthreads();
    uint32_t tmem;
    asm("ld.shared.b32 %0, [%1];" : "=r"(tmem) : "r"(sb));

    auto load_stage = [&](int p, int buf) {
        if (p < P) {
            const uint32_t st = sb + 4096 + buf * STAGE;
            const char* sA = reinterpret_cast<const char*>(a.A)
                           + ((size_t)p * NTOK + m0) * 128;
            const char* sB = reinterpret_cast<const char*>(a.B)
                           + ((size_t)p * (size_t)Ntot + n0) * 128;
            const int t16 = tid << 4;
#pragma unroll
            for (int j = 0; j < ABYTES / 4096; j++)
                cp16(st + t16 + (j << 12), sA + t16 + (j << 12));
#pragma unroll
            for (int j = 0; j < BBYTES / 4096; j++)
                cp16(st + ABYTES + t16 + (j << 12), sB + t16 + (j << 12));
        }
        cp_commit();
    };

    for (int s = 0; s < NSTAGE - 1; s++) load_stage(s, s);

    for (int p = 0; p < P; p++) {
        const int buf = p % NSTAGE;
        cp_wait<NSTAGE - 2>();
        asm volatile("fence.proxy.async.shared::cta;" ::: "memory");
        __syncthreads();
        if (tid == 0) {
            const uint32_t st = sb + 4096 + buf * STAGE;
            const uint64_t ad0 = mkdesc(st);
            const uint64_t bd0 = mkdesc(st + ABYTES);
#pragma unroll
            for (int mh = 0; mh < MTILE / 128; mh++) {
                const uint64_t ad = ad0 + mh * 1024;
#pragma unroll
                for (int nh = 0; nh < 2; nh++) {
                    const uint32_t dt = tmem + mh * 256 + nh * 128;
                    const uint64_t bd = bd0 + nh * 1024;
                    mma_bf16(dt, ad + 0, bd + 0, IDESC_BF16, (p == 0) ? 0u : 1u);
                    mma_bf16(dt, ad + 2, bd + 2, IDESC_BF16, 1u);   // b0*b0
                    mma_bf16(dt, ad + 0, bd + 4, IDESC_BF16, 1u);   // b0*b1
                    mma_bf16(dt, ad + 2, bd + 6, IDESC_BF16, 1u);
                    mma_bf16(dt, ad + 4, bd + 0, IDESC_BF16, 1u);   // b1*b0
                    mma_bf16(dt, ad + 6, bd + 2, IDESC_BF16, 1u);
                }
            }
            tc_commit(sb + 16 + buf * 8);
        }
        if (p >= 1) {
            const int q = p - 1;
            mbar_wait(sb + 16 + (q % NSTAGE) * 8, (q / NSTAGE) & 1);
        }
        load_stage(p + NSTAGE - 1, (p + NSTAGE - 1) % NSTAGE);
    }
    {
        const int q = P - 1;
        mbar_wait(sb + 16 + (q % NSTAGE) * 8, (q / NSTAGE) & 1);
    }

    // ---- epilogue: paired LDTM -> regs (+bias) -> swizzled SMEM -> STG ------
    tc_fence_after();
    float4* eb = reinterpret_cast<float4*>(smem + 4096);
    const int sp = w & 3;
    const int cb0 = (w < 4) ? 0 : 128;
    const int mrow = sp * 32 + lane;
#pragma unroll
    for (int mh = 0; mh < MTILE / 128; mh++) {
#pragma unroll
        for (int cbp = 0; cbp < 2; cbp++) {
            const int colbase = cb0 + cbp * 64;
            uint32_t r0[32], r1[32];
            ldtm32(r0, tmem + mh * 256 + colbase);
            ldtm32(r1, tmem + mh * 256 + colbase + 32);
            tc_wait_ld();
#pragma unroll
            for (int j = 0; j < 8; j++) {
                float4 v;
                v.x = __uint_as_float(r0[4 * j + 0]) + bias_s[colbase + 4 * j + 0];
                v.y = __uint_as_float(r0[4 * j + 1]) + bias_s[colbase + 4 * j + 1];
                v.z = __uint_as_float(r0[4 * j + 2]) + bias_s[colbase + 4 * j + 2];
                v.w = __uint_as_float(r0[4 * j + 3]) + bias_s[colbase + 4 * j + 3];
                const int c4 = (colbase >> 2) + j;
                eb[mrow * 64 + (c4 ^ (mrow & 7))] = v;
            }
#pragma unroll
            for (int j = 0; j < 8; j++) {
                float4 v;
                v.x = __uint_as_float(r1[4 * j + 0]) + bias_s[colbase + 32 + 4 * j + 0];
                v.y = __uint_as_float(r1[4 * j + 1]) + bias_s[colbase + 32 + 4 * j + 1];
                v.z = __uint_as_float(r1[4 * j + 2]) + bias_s[colbase + 32 + 4 * j + 2];
                v.w = __uint_as_float(r1[4 * j + 3]) + bias_s[colbase + 32 + 4 * j + 3];
                const int c4 = ((colbase + 32) >> 2) + j;
                eb[mrow * 64 + (c4 ^ (mrow & 7))] = v;
            }
        }
        __syncthreads();
#pragma unroll
        for (int i = 0; i < 32; i++) {
            const int idx = tid + (i << 8);
            const int row = idx >> 6, c4 = idx & 63;
            const float4 v = eb[row * 64 + (c4 ^ (row & 7))];
            *reinterpret_cast<float4*>(
                a.C + (size_t)(m0 + mh * 128 + row) * Ntot + n0 + (c4 << 2)) = v;
        }
        __syncthreads();
    }
    if (w == 0) tc_dealloc(tmem, TCOLS);
}

// ---------------- split-K reduction: out = p0 + p1 + bias --------------------
__global__ void reduce_out2(const float4* __restrict__ p0, const float4* __restrict__ p1,
                            const float* __restrict__ bias, float4* __restrict__ out) {
    const int i = blockIdx.x * 256 + threadIdx.x;
    const float4 av = p0[i], bv = p1[i];
    const float4 cv = *reinterpret_cast<const float4*>(bias + (i & 63) * 4);
    float4 v;
    v.x = av.x + bv.x + cv.x;
    v.y = av.y + bv.y + cv.y;
    v.z = av.z + bv.z + cv.z;
    v.w = av.w + bv.w + cv.w;
    out[i] = v;
}

// ---------------- bf16 2-split + panel-swizzle writers -----------------------
__device__ __forceinline__ void split2(float x, bf16& b0, bf16& b1) {
    b0 = __float2bfloat16(x);
    b1 = __float2bfloat16(x - __bfloat162float(b0));
}
__device__ __forceinline__ void store_split4(char* base, int row, int kk,
                                             const float4& x) {
    bf16 b0[4], b1[4];
    split2(x.x, b0[0], b1[0]);
    split2(x.y, b0[1], b1[1]);
    split2(x.z, b0[2], b1[2]);
    split2(x.w, b0[3], b1[3]);
    const int c  = kk >> 3;
    const int bo = (kk & 7) * 2;
    *reinterpret_cast<uint2*>(base + ((c ^ (row & 7)) << 4) + bo) =
        *reinterpret_cast<uint2*>(b0);
    *reinterpret_cast<uint2*>(base + (((c + 4) ^ (row & 7)) << 4) + bo) =
        *reinterpret_cast<uint2*>(b1);
}

__global__ void split_inputs(const float4* __restrict__ q, const float4* __restrict__ k,
                             const float4* __restrict__ v,
                             const unsigned char* __restrict__ mask) {
    if (blockIdx.x == 0 && blockIdx.y == 0 && threadIdx.x < 32) {
        int lane = threadIdx.x;
        int big = 0, nzoff = 0;
        for (int i = lane; i < 1024; i += 32) {
            unsigned char mv = mask[i];
            if (mv > 1) big = 1;
            if ((i & 3) != 0 && mv != 0) nzoff = 1;
        }
        big   = __any_sync(0xffffffffu, big);
        nzoff = __any_sync(0xffffffffu, nzoff);
        if (lane == 0) g_mask_mode = big ? 0 : (nzoff ? 2 : 1);
    }
    const int i = blockIdx.x * 256 + threadIdx.x;
    const float4* s;
    bf16* dst;
    if (blockIdx.y == 0)      { s = q; dst = g_Aq; }
    else if (blockIdx.y == 1) { s = k; dst = g_Ak; }
    else                      { s = v; dst = g_Av; }
    const int r = i >> 6, j0 = (i & 63) << 2;
    const int p = j0 >> 5, kk = j0 & 31;
    char* base = reinterpret_cast<char*>(dst) + (((size_t)p * NTOK + r) << 7);
    store_split4(base, r, kk, s[i]);
}

__global__ void wsplit(const float* __restrict__ Wq, const float* __restrict__ Wk,
                       const float* __restrict__ Wv, const float* __restrict__ Wo) {
    const int z = blockIdx.z;
    const float* W; bf16* T; int K_, N_;
    if (z == 0)      { W = Wq; T = g_Bq; K_ = DMODEL; N_ = DHID; }
    else if (z == 1) { W = Wk; T = g_Bk; K_ = DMODEL; N_ = DHID; }
    else if (z == 2) { W = Wv; T = g_Bv; K_ = DMODEL; N_ = DHID; }
    else             { W = Wo; T = g_Bo; K_ = DHID;  N_ = DMODEL; }
    const int bx = blockIdx.x * 32;
    const int by = blockIdx.y * 32;
    if (bx >= N_ || by >= K_) return;
    __shared__ float t[32][33];
    const int tx = threadIdx.x, ty = threadIdx.y;
#pragma unroll
    for (int i = 0; i < 4; i++)
        t[ty + i * 8][tx] = W[(size_t)(by + ty + i * 8) * N_ + bx + tx];
    __syncthreads();
#pragma unroll
    for (int i = 0; i < 4; i++) {
        const int n = bx + ty + i * 8;
        const int kx = by + tx;
        const float x = t[tx][ty + i * 8];
        bf16 b0, b1;
        split2(x, b0, b1);
        const int p = kx >> 5, kk = kx & 31;
        const int c = kk >> 3, bo = (kk & 7) * 2;
        char* base = reinterpret_cast<char*>(T) + (((size_t)p * N_ + n) << 7);
        *reinterpret_cast<bf16*>(base + ((c ^ (n & 7)) << 4) + bo) = b0;
        *reinterpret_cast<bf16*>(base + (((c + 4) ^ (n & 7)) << 4) + bo) = b1;
    }
}

// ---------------- warp-per-token attention, folded reduction (round 13) ------
__global__ void __launch_bounds__(384, 1) attn_warp(const void* __restrict__ maskp) {
    const int lane = threadIdx.x & 31;
    const int t = blockIdx.x * 12 + (threadIdx.x >> 5);
    if (t >= NTOK) return;

    const float4* qb = reinterpret_cast<const float4*>(g_Q  + (size_t)t * DHID);
    const float4* kb = reinterpret_cast<const float4*>(g_Kp + (size_t)t * DHID);
    const float4* vb = reinterpret_cast<const float4*>(g_Vp + (size_t)t * DHID);
    const unsigned FULL = 0xffffffffu;

    float4 q0[8], q1[8];
#pragma unroll
    for (int h = 0; h < 8; h++) {
        q0[h] = qb[h * 64 + lane * 2];
        q1[h] = qb[h * 64 + lane * 2 + 1];
    }

    float own_p[8];
#pragma unroll
    for (int g = 0; g < 8; g++) {
        const float4 k0 = kb[g * 64 + lane * 2];
        const float4 k1 = kb[g * 64 + lane * 2 + 1];
        float s[8];
#pragma unroll
        for (int h = 0; h < 8; h++)
            s[h] = q0[h].x * k0.x + q0[h].y * k0.y + q0[h].z * k0.z + q0[h].w * k0.w
                 + q1[h].x * k1.x + q1[h].y * k1.y + q1[h].z * k1.z + q1[h].w * k1.w;
        const bool b4 = (lane & 16) != 0;
        float a[4];
#pragma unroll
        for (int j = 0; j < 4; j++) {
            const float sel = b4 ? s[j] : s[j + 4];
            const float r = __shfl_xor_sync(FULL, sel, 16);
            a[j] = (b4 ? s[j + 4] : s[j]) + r;
        }
        const bool b3 = (lane & 8) != 0;
        float bb[2];
#pragma unroll
        for (int j = 0; j < 2; j++) {
            const float sel = b3 ? a[j] : a[j + 2];
            const float r = __shfl_xor_sync(FULL, sel, 8);
            bb[j] = (b3 ? a[j + 2] : a[j]) + r;
        }
        const bool b2 = (lane & 4) != 0;
        {
            const float sel = b2 ? bb[0] : bb[1];
            const float r = __shfl_xor_sync(FULL, sel, 4);
            float c = (b2 ? bb[1] : bb[0]) + r;
            c += __shfl_xor_sync(FULL, c, 2);
            c += __shfl_xor_sync(FULL, c, 1);
            own_p[g] = c * 0.0625f;
        }
    }

    bool mv;
    {
        int mode = g_mask_mode;
        if (mode == 0)      mv = reinterpret_cast<const float*>(maskp)[t] != 0.0f;
        else if (mode == 1) mv = reinterpret_cast<const int*>(maskp)[t] != 0;
        else                mv = reinterpret_cast<const unsigned char*>(maskp)[t] != 0;
    }
    {
        float mx = -3.4e38f;
#pragma unroll
        for (int g = 0; g < 8; g++) {
            own_p[g] = mv ? own_p[g] : -1.0e9f;
            mx = fmaxf(mx, own_p[g]);
        }
        float sum = 0.f;
#pragma unroll
        for (int g = 0; g < 8; g++) { own_p[g] = expf(own_p[g] - mx); sum += own_p[g]; }
        const float inv = 1.0f / sum;
#pragma unroll
        for (int g = 0; g < 8; g++) own_p[g] *= inv;
    }

    float4 x0[8], x1[8];
#pragma unroll
    for (int h = 0; h < 8; h++) {
        x0[h] = make_float4(0.f, 0.f, 0.f, 0.f);
        x1[h] = make_float4(0.f, 0.f, 0.f, 0.f);
    }
#pragma unroll
    for (int g = 0; g < 8; g++) {
        const float4 v0 = vb[g * 64 + lane * 2];
        const float4 v1 = vb[g * 64 + lane * 2 + 1];
#pragma unroll
        for (int h = 0; h < 8; h++) {
            const float pg = __shfl_sync(FULL, own_p[g], h << 2);
            x0[h].x += pg * v0.x; x0[h].y += pg * v0.y;
            x0[h].z += pg * v0.z; x0[h].w += pg * v0.w;
            x1[h].x += pg * v1.x; x1[h].y += pg * v1.y;
            x1[h].z += pg * v1.z; x1[h].w += pg * v1.w;
        }
    }

    const int b = t >> 11, sIdx = t & 2047;
    const int kidx = (sIdx & 7) * 256 + lane * 8;
    const int pp = kidx >> 5, c = (kidx & 31) >> 3;
#pragma unroll
    for (int h = 0; h < 8; h++) {
        const int ar = b * 2048 + h * 256 + (sIdx >> 3);
        char* base = reinterpret_cast<char*>(g_AX) + (((size_t)pp * NTOK + ar) << 7);
        bf16 b0[8], b1[8];
        split2(x0[h].x, b0[0], b1[0]); split2(x0[h].y, b0[1], b1[1]);
        split2(x0[h].z, b0[2], b1[2]); split2(x0[h].w, b0[3], b1[3]);
        split2(x1[h].x, b0[4], b1[4]); split2(x1[h].y, b0[5], b1[5]);
        split2(x1[h].z, b0[6], b1[6]); split2(x1[h].w, b0[7], b1[7]);
        *reinterpret_cast<uint4*>(base + ((c ^ (ar & 7)) << 4)) =
            *reinterpret_cast<uint4*>(b0);
        *reinterpret_cast<uint4*>(base + (((c + 4) ^ (ar & 7)) << 4)) =
            *reinterpret_cast<uint4*>(b1);
    }
}

// ---------------- launch ------------------------------------------------------
extern "C" void kernel_launch(void* const* d_in, const int* in_sizes, int n_in,
                              void* d_out, int out_size) {
    const float* query = (const float*)d_in[0];
    const float* key   = (const float*)d_in[1];
    const float* value = (const float*)d_in[2];
    const void*  mask  = d_in[3];
    const float* Wq = (const float*)d_in[4];
    const float* bq = (const float*)d_in[5];
    const float* Wk = (const float*)d_in[6];
    const float* bk = (const float*)d_in[7];
    const float* Wv = (const float*)d_in[8];
    const float* bv = (const float*)d_in[9];
    const float* Wo = (const float*)d_in[10];
    const float* bo = (const float*)d_in[11];
    float* out = (float*)d_out;

    cudaFuncSetAttribute(gemm_ps<256, 3>,
                         cudaFuncAttributeMaxDynamicSharedMemorySize, GEMM_SMEM);

    split_inputs<<<dim3((NTOK * DMODEL / 4) / 256, 3), 256>>>(
        (const float4*)query, (const float4*)key, (const float4*)value,
        (const unsigned char*)mask);
    wsplit<<<dim3(64, 64, 4), dim3(32, 8)>>>(Wq, Wk, Wv, Wo);

    bf16 *Aq, *Ak, *Av, *AX, *Bq, *Bk, *Bv, *Bo;
    float *Qp, *Kp, *Vp, *Part, *Zero;
    cudaGetSymbolAddress((void**)&Aq, g_Aq);
    cudaGetSymbolAddress((void**)&Ak, g_Ak);
    cudaGetSymbolAddress((void**)&Av, g_Av);
    cudaGetSymbolAddress((void**)&AX, g_AX);
    cudaGetSymbolAddress((void**)&Bq, g_Bq);
    cudaGetSymbolAddress((void**)&Bk, g_Bk);
    cudaGetSymbolAddress((void**)&Bv, g_Bv);
    cudaGetSymbolAddress((void**)&Bo, g_Bo);
    cudaGetSymbolAddress((void**)&Qp, g_Q);
    cudaGetSymbolAddress((void**)&Kp, g_Kp);
    cudaGetSymbolAddress((void**)&Vp, g_Vp);
    cudaGetSymbolAddress((void**)&Part, g_part);
    cudaGetSymbolAddress((void**)&Zero, g_zero);

    // merged Q/K/V projections: M=256 tiles, grid (8, 64, 3)   [round-13 config]
    GemmArgs3 qkv;
    qkv.g[0] = { Aq, Bq, bq, Qp };
    qkv.g[1] = { Ak, Bk, bk, Kp };
    qkv.g[2] = { Av, Bv, bv, Vp };
    gemm_ps<256, 3><<<dim3(DHID / 256, NTOK / 256, 3), 256, GEMM_SMEM>>>(
        qkv, DMODEL, DHID);

    // warp-per-token attention: 12 warps/CTA   [round-13 config]
    attn_warp<<<(NTOK + 11) / 12, 384>>>(mask);

    // output projection: 2-way split-K (32 panels each), M=256, grid (1,64,2)
    GemmArgs3 oarg;
    for (int s = 0; s < 2; s++) {
        oarg.g[s].A = AX + (size_t)s * 32 * NTOK * 64;
        oarg.g[s].B = Bo + (size_t)s * 32 * DMODEL * 64;
        oarg.g[s].bias = Zero;
        oarg.g[s].C = Part + (size_t)s * NTOK * DMODEL;
    }
    oarg.g[2] = oarg.g[0];
    gemm_ps<256, 3><<<dim3(DMODEL / 256, NTOK / 256, 2), 256, GEMM_SMEM>>>(
        oarg, DHID / 2, DMODEL);

    reduce_out2<<<NTOK * DMODEL / 4 / 256, 256>>>(
        (const float4*)Part,
        (const float4*)(Part + (size_t)NTOK * DMODEL),
        bo, (float4*)out);
}

// round 16
// speedup vs baseline: 1.3774x; 1.0241x over previous
#include <cuda_runtime.h>
#include <cuda_bf16.h>
#include <cstdint>

#define NTOK   16384   // B*S
#define DMODEL 256
#define NHEADS 8
#define DHID   2048    // DMODEL*NHEADS

#if defined(__CUDA_ARCH_SPECIFIC__) || defined(__CUDA_ARCH_FAMILY_SPECIFIC__)
#define HAS_TC05 1
#else
#define HAS_TC05 0
#endif

typedef __nv_bfloat16 bf16;

// ---------------- device-global scratch (allocation-free) -------------------
__device__ float g_Q [(size_t)NTOK * DHID];
__device__ float g_Kp[(size_t)NTOK * DHID];
__device__ float g_Vp[(size_t)NTOK * DHID];

// Panel-major pre-swizzled bf16 2-split operands.
// arr[(p * ROWS + row) * 64 .. +64) bf16 = one 128B SW128 row
// [b0 k(32p..32p+31) | b1 same], chunk c stored at byte ((c ^ (row&7))<<4).
__device__ bf16 g_Aq[(size_t)8  * NTOK * 64];
__device__ bf16 g_Ak[(size_t)8  * NTOK * 64];
__device__ bf16 g_Av[(size_t)8  * NTOK * 64];
__device__ bf16 g_AX[(size_t)64 * NTOK * 64];
__device__ bf16 g_Bq[(size_t)8  * DHID * 64];
__device__ bf16 g_Bk[(size_t)8  * DHID * 64];
__device__ bf16 g_Bv[(size_t)8  * DHID * 64];
__device__ bf16 g_Bo[(size_t)64 * DMODEL * 64];

__device__ int g_mask_mode;   // 0=float32, 1=int32, 2=uint8/bool

// ---------------- small PTX helpers -----------------------------------------
__device__ __forceinline__ uint32_t smem_u32(const void* p) {
    uint32_t a;
    asm("{ .reg .u64 t; cvta.to.shared.u64 t, %1; cvt.u32.u64 %0, t; }"
        : "=r"(a) : "l"(p));
    return a;
}
__device__ __forceinline__ void cp16(uint32_t dst, const void* src) {
    asm volatile("cp.async.cg.shared.global [%0], [%1], 16;" :: "r"(dst), "l"(src));
}
__device__ __forceinline__ void cp_commit() {
    asm volatile("cp.async.commit_group;" ::: "memory");
}
template <int N> __device__ __forceinline__ void cp_wait() {
    asm volatile("cp.async.wait_group %0;" :: "n"(N) : "memory");
}
__device__ __forceinline__ void mbar_init(uint32_t a, uint32_t cnt) {
    asm volatile("mbarrier.init.shared.b64 [%0], %1;" :: "r"(a), "r"(cnt) : "memory");
}
__device__ __forceinline__ void mbar_wait(uint32_t a, uint32_t ph) {
    asm volatile(
        "{\n\t.reg .pred P1;\n"
        "LW%=:\n\tmbarrier.try_wait.parity.acquire.cta.shared::cta.b64 P1, [%0], %1;\n"
        "\t@P1 bra LD%=;\n\tbra LW%=;\n"
        "LD%=:\n\t}"
        :: "r"(a), "r"(ph) : "memory");
}

// ---- tcgen05 wrappers (arch-specific pass only) -----------------------------
__device__ __forceinline__ void tc_alloc(uint32_t slot, uint32_t ncols) {
#if HAS_TC05
    asm volatile("tcgen05.alloc.cta_group::1.sync.aligned.shared::cta.b32 [%0], %1;"
                 :: "r"(slot), "r"(ncols) : "memory");
#endif
}
__device__ __forceinline__ void tc_dealloc(uint32_t tmem, uint32_t ncols) {
#if HAS_TC05
    asm volatile("tcgen05.dealloc.cta_group::1.sync.aligned.b32 %0, %1;"
                 :: "r"(tmem), "r"(ncols));
#endif
}
__device__ __forceinline__ void tc_commit(uint32_t mbar) {
#if HAS_TC05
    asm volatile("tcgen05.commit.cta_group::1.mbarrier::arrive::one.shared::cluster.b64 [%0];"
                 :: "r"(mbar) : "memory");
#else
    asm volatile("mbarrier.arrive.shared.b64 _, [%0];" :: "r"(mbar) : "memory");
#endif
}
__device__ __forceinline__ void mma_bf16(uint32_t d, uint64_t ad, uint64_t bd,
                                         uint32_t idesc, uint32_t acc) {
#if HAS_TC05
    asm volatile(
        "{\n\t.reg .pred p;\n"
        "\tsetp.ne.u32 p, %4, 0;\n"
        "\ttcgen05.mma.cta_group::1.kind::f16 [%0], %1, %2, %3, p;\n\t}"
        :: "r"(d), "l"(ad), "l"(bd), "r"(idesc), "r"(acc) : "memory");
#endif
}
__device__ __forceinline__ void ldtm32(uint32_t* r, uint32_t a) {
#if HAS_TC05
    asm volatile(
        "tcgen05.ld.sync.aligned.32x32b.x32.b32 "
        "{%0, %1, %2, %3, %4, %5, %6, %7, %8, %9, %10, %11, %12, %13, %14, %15, "
        "%16, %17, %18, %19, %20, %21, %22, %23, %24, %25, %26, %27, %28, %29, %30, %31}, [%32];"
        : "=r"(r[0]), "=r"(r[1]), "=r"(r[2]), "=r"(r[3]), "=r"(r[4]), "=r"(r[5]),
          "=r"(r[6]), "=r"(r[7]), "=r"(r[8]), "=r"(r[9]), "=r"(r[10]), "=r"(r[11]),
          "=r"(r[12]), "=r"(r[13]), "=r"(r[14]), "=r"(r[15]), "=r"(r[16]), "=r"(r[17]),
          "=r"(r[18]), "=r"(r[19]), "=r"(r[20]), "=r"(r[21]), "=r"(r[22]), "=r"(r[23]),
          "=r"(r[24]), "=r"(r[25]), "=r"(r[26]), "=r"(r[27]), "=r"(r[28]), "=r"(r[29]),
          "=r"(r[30]), "=r"(r[31])
        : "r"(a));
#else
#pragma unroll
    for (int i = 0; i < 32; i++) r[i] = 0u;
#endif
}
__device__ __forceinline__ void tc_wait_ld() {
#if HAS_TC05
    asm volatile("tcgen05.wait::ld.sync.aligned;" ::: "memory");
#endif
}
__device__ __forceinline__ void tc_fence_after() {
#if HAS_TC05
    asm volatile("tcgen05.fence::after_thread_sync;" ::: "memory");
#endif
}

// SW128 K-major SMEM descriptor (LBO=1, SBO=64, version=1, layout=SW128)
__device__ __forceinline__ uint64_t mkdesc(uint32_t addr) {
    const uint64_t BASE = (2ull << 61) | (1ull << 46) | (64ull << 32) | (1ull << 16);
    return BASE | ((uint64_t)(addr >> 4) & 0x3FFF);
}

// idesc kind::f16: cF32(bit4), aBF16(bit7), bBF16(bit10), N=128 (16<<17), M=128 (8<<24)
#define IDESC_BF16 ((1u << 4) | (1u << 7) | (1u << 10) | (16u << 17) | (8u << 24))

// ---------------- GEMM: pre-swizzled panels, identity cp.async ---------------
struct GemmArgs {
    const bf16 *A, *B;
    const float* bias;
    float* C;
};
struct GemmArgs3 { GemmArgs g[3]; };

#define GEMM_SMEM 200704   // 4096 + 3*64KB (M256) == 4096 + 4*48KB (M128)

template <int MTILE, int NSTAGE>
__global__ void __launch_bounds__(256, 1) gemm_ps(GemmArgs3 args, int K, int Ntot) {
    constexpr int ABYTES = MTILE * 128;
    constexpr int BBYTES = 256 * 128;
    constexpr int STAGE  = ABYTES + BBYTES;
    constexpr int TCOLS  = (MTILE / 128) * 256;
    extern __shared__ __align__(1024) char smem[];
    const GemmArgs a = args.g[blockIdx.z];
    const uint32_t sb = smem_u32(smem);
    const int tid = threadIdx.x;
    const int w = tid >> 5, lane = tid & 31;
    const int m0 = blockIdx.y * MTILE, n0 = blockIdx.x * 256;
    const int P = K >> 5;

    if (tid == 0)
        for (int i = 0; i < NSTAGE; i++) mbar_init(sb + 16 + i * 8, 1);
    if (w == 0) tc_alloc(sb, TCOLS);
    float* bias_s = reinterpret_cast<float*>(smem + 1024);
    bias_s[tid] = a.bias[n0 + tid];
    __syncthreads();
    uint32_t tmem;
    asm("ld.shared.b32 %0, [%1];" : "=r"(tmem) : "r"(sb));

    auto load_stage = [&](int p, int buf) {
        if (p < P) {
            const uint32_t st = sb + 4096 + buf * STAGE;
            const char* sA = reinterpret_cast<const char*>(a.A)
                           + ((size_t)p * NTOK + m0) * 128;
            const char* sB = reinterpret_cast<const char*>(a.B)
                           + ((size_t)p * (size_t)Ntot + n0) * 128;
            const int t16 = tid << 4;
#pragma unroll
            for (int j = 0; j < ABYTES / 4096; j++)
                cp16(st + t16 + (j << 12), sA + t16 + (j << 12));
#pragma unroll
            for (int j = 0; j < BBYTES / 4096; j++)
                cp16(st + ABYTES + t16 + (j << 12), sB + t16 + (j << 12));
        }
        cp_commit();
    };

    for (int s = 0; s < NSTAGE - 1; s++) load_stage(s, s);

    for (int p = 0; p < P; p++) {
        const int buf = p % NSTAGE;
        cp_wait<NSTAGE - 2>();
        asm volatile("fence.proxy.async.shared::cta;" ::: "memory");
        __syncthreads();
        if (tid == 0) {
            const uint32_t st = sb + 4096 + buf * STAGE;
            const uint64_t ad0 = mkdesc(st);
            const uint64_t bd0 = mkdesc(st + ABYTES);
#pragma unroll
            for (int mh = 0; mh < MTILE / 128; mh++) {
                const uint64_t ad = ad0 + mh * 1024;
#pragma unroll
                for (int nh = 0; nh < 2; nh++) {
                    const uint32_t dt = tmem + mh * 256 + nh * 128;
                    const uint64_t bd = bd0 + nh * 1024;
                    mma_bf16(dt, ad + 0, bd + 0, IDESC_BF16, (p == 0) ? 0u : 1u);
                    mma_bf16(dt, ad + 2, bd + 2, IDESC_BF16, 1u);   // b0*b0
                    mma_bf16(dt, ad + 0, bd + 4, IDESC_BF16, 1u);   // b0*b1
                    mma_bf16(dt, ad + 2, bd + 6, IDESC_BF16, 1u);
                    mma_bf16(dt, ad + 4, bd + 0, IDESC_BF16, 1u);   // b1*b0
                    mma_bf16(dt, ad + 6, bd + 2, IDESC_BF16, 1u);
                }
            }
            tc_commit(sb + 16 + buf * 8);
        }
        if (p >= 1) {
            const int q = p - 1;
            mbar_wait(sb + 16 + (q % NSTAGE) * 8, (q / NSTAGE) & 1);
        }
        load_stage(p + NSTAGE - 1, (p + NSTAGE - 1) % NSTAGE);
    }
    {
        const int q = P - 1;
        mbar_wait(sb + 16 + (q % NSTAGE) * 8, (q / NSTAGE) & 1);
    }

    // ---- epilogue: paired LDTM -> regs (+bias) -> swizzled SMEM -> STG ------
    tc_fence_after();
    float4* eb = reinterpret_cast<float4*>(smem + 4096);
    const int sp = w & 3;
    const int cb0 = (w < 4) ? 0 : 128;
    const int mrow = sp * 32 + lane;
#pragma unroll
    for (int mh = 0; mh < MTILE / 128; mh++) {
#pragma unroll
        for (int cbp = 0; cbp < 2; cbp++) {
            const int colbase = cb0 + cbp * 64;
            uint32_t r0[32], r1[32];
            ldtm32(r0, tmem + mh * 256 + colbase);
            ldtm32(r1, tmem + mh * 256 + colbase + 32);
            tc_wait_ld();
#pragma unroll
            for (int j = 0; j < 8; j++) {
                float4 v;
                v.x = __uint_as_float(r0[4 * j + 0]) + bias_s[colbase + 4 * j + 0];
                v.y = __uint_as_float(r0[4 * j + 1]) + bias_s[colbase + 4 * j + 1];
                v.z = __uint_as_float(r0[4 * j + 2]) + bias_s[colbase + 4 * j + 2];
                v.w = __uint_as_float(r0[4 * j + 3]) + bias_s[colbase + 4 * j + 3];
                const int c4 = (colbase >> 2) + j;
                eb[mrow * 64 + (c4 ^ (mrow & 7))] = v;
            }
#pragma unroll
            for (int j = 0; j < 8; j++) {
                float4 v;
                v.x = __uint_as_float(r1[4 * j + 0]) + bias_s[colbase + 32 + 4 * j + 0];
                v.y = __uint_as_float(r1[4 * j + 1]) + bias_s[colbase + 32 + 4 * j + 1];
                v.z = __uint_as_float(r1[4 * j + 2]) + bias_s[colbase + 32 + 4 * j + 2];
                v.w = __uint_as_float(r1[4 * j + 3]) + bias_s[colbase + 32 + 4 * j + 3];
                const int c4 = ((colbase + 32) >> 2) + j;
                eb[mrow * 64 + (c4 ^ (mrow & 7))] = v;
            }
        }
        __syncthreads();
#pragma unroll
        for (int i = 0; i < 32; i++) {
            const int idx = tid + (i << 8);
            const int row = idx >> 6, c4 = idx & 63;
            const float4 v = eb[row * 64 + (c4 ^ (row & 7))];
            *reinterpret_cast<float4*>(
                a.C + (size_t)(m0 + mh * 128 + row) * Ntot + n0 + (c4 << 2)) = v;
        }
        __syncthreads();
    }
    if (w == 0) tc_dealloc(tmem, TCOLS);
}

// ---------------- bf16 2-split + panel-swizzle writers -----------------------
__device__ __forceinline__ void split2(float x, bf16& b0, bf16& b1) {
    b0 = __float2bfloat16(x);
    b1 = __float2bfloat16(x - __bfloat162float(b0));
}
__device__ __forceinline__ void store_split4(char* base, int row, int kk,
                                             const float4& x) {
    bf16 b0[4], b1[4];
    split2(x.x, b0[0], b1[0]);
    split2(x.y, b0[1], b1[1]);
    split2(x.z, b0[2], b1[2]);
    split2(x.w, b0[3], b1[3]);
    const int c  = kk >> 3;
    const int bo = (kk & 7) * 2;
    *reinterpret_cast<uint2*>(base + ((c ^ (row & 7)) << 4) + bo) =
        *reinterpret_cast<uint2*>(b0);
    *reinterpret_cast<uint2*>(base + (((c + 4) ^ (row & 7)) << 4) + bo) =
        *reinterpret_cast<uint2*>(b1);
}

__global__ void split_inputs(const float4* __restrict__ q, const float4* __restrict__ k,
                             const float4* __restrict__ v,
                             const unsigned char* __restrict__ mask) {
    if (blockIdx.x == 0 && blockIdx.y == 0 && threadIdx.x < 32) {
        int lane = threadIdx.x;
        int big = 0, nzoff = 0;
        for (int i = lane; i < 1024; i += 32) {
            unsigned char mv = mask[i];
            if (mv > 1) big = 1;
            if ((i & 3) != 0 && mv != 0) nzoff = 1;
        }
        big   = __any_sync(0xffffffffu, big);
        nzoff = __any_sync(0xffffffffu, nzoff);
        if (lane == 0) g_mask_mode = big ? 0 : (nzoff ? 2 : 1);
    }
    const int i = blockIdx.x * 256 + threadIdx.x;
    const float4* s;
    bf16* dst;
    if (blockIdx.y == 0)      { s = q; dst = g_Aq; }
    else if (blockIdx.y == 1) { s = k; dst = g_Ak; }
    else                      { s = v; dst = g_Av; }
    const int r = i >> 6, j0 = (i & 63) << 2;
    const int p = j0 >> 5, kk = j0 & 31;
    char* base = reinterpret_cast<char*>(dst) + (((size_t)p * NTOK + r) << 7);
    store_split4(base, r, kk, s[i]);
}

__global__ void wsplit(const float* __restrict__ Wq, const float* __restrict__ Wk,
                       const float* __restrict__ Wv, const float* __restrict__ Wo) {
    const int z = blockIdx.z;
    const float* W; bf16* T; int K_, N_;
    if (z == 0)      { W = Wq; T = g_Bq; K_ = DMODEL; N_ = DHID; }
    else if (z == 1) { W = Wk; T = g_Bk; K_ = DMODEL; N_ = DHID; }
    else if (z == 2) { W = Wv; T = g_Bv; K_ = DMODEL; N_ = DHID; }
    else             { W = Wo; T = g_Bo; K_ = DHID;  N_ = DMODEL; }
    const int bx = blockIdx.x * 32;
    const int by = blockIdx.y * 32;
    if (bx >= N_ || by >= K_) return;
    __shared__ float t[32][33];
    const int tx = threadIdx.x, ty = threadIdx.y;
#pragma unroll
    for (int i = 0; i < 4; i++)
        t[ty + i * 8][tx] = W[(size_t)(by + ty + i * 8) * N_ + bx + tx];
    __syncthreads();
#pragma unroll
    for (int i = 0; i < 4; i++) {
        const int n = bx + ty + i * 8;
        const int kx = by + tx;
        const float x = t[tx][ty + i * 8];
        bf16 b0, b1;
        split2(x, b0, b1);
        const int p = kx >> 5, kk = kx & 31;
        const int c = kk >> 3, bo = (kk & 7) * 2;
        char* base = reinterpret_cast<char*>(T) + (((size_t)p * N_ + n) << 7);
        *reinterpret_cast<bf16*>(base + ((c ^ (n & 7)) << 4) + bo) = b0;
        *reinterpret_cast<bf16*>(base + (((c + 4) ^ (n & 7)) << 4) + bo) = b1;
    }
}

// ---------------- warp-per-token attention, folded reduction (round 13) ------
__global__ void __launch_bounds__(384, 1) attn_warp(const void* __restrict__ maskp) {
    const int lane = threadIdx.x & 31;
    const int t = blockIdx.x * 12 + (threadIdx.x >> 5);
    if (t >= NTOK) return;

    const float4* qb = reinterpret_cast<const float4*>(g_Q  + (size_t)t * DHID);
    const float4* kb = reinterpret_cast<const float4*>(g_Kp + (size_t)t * DHID);
    const float4* vb = reinterpret_cast<const float4*>(g_Vp + (size_t)t * DHID);
    const unsigned FULL = 0xffffffffu;

    float4 q0[8], q1[8];
#pragma unroll
    for (int h = 0; h < 8; h++) {
        q0[h] = qb[h * 64 + lane * 2];
        q1[h] = qb[h * 64 + lane * 2 + 1];
    }

    float own_p[8];
#pragma unroll
    for (int g = 0; g < 8; g++) {
        const float4 k0 = kb[g * 64 + lane * 2];
        const float4 k1 = kb[g * 64 + lane * 2 + 1];
        float s[8];
#pragma unroll
        for (int h = 0; h < 8; h++)
            s[h] = q0[h].x * k0.x + q0[h].y * k0.y + q0[h].z * k0.z + q0[h].w * k0.w
                 + q1[h].x * k1.x + q1[h].y * k1.y + q1[h].z * k1.z + q1[h].w * k1.w;
        const bool b4 = (lane & 16) != 0;
        float a[4];
#pragma unroll
        for (int j = 0; j < 4; j++) {
            const float sel = b4 ? s[j] : s[j + 4];
            const float r = __shfl_xor_sync(FULL, sel, 16);
            a[j] = (b4 ? s[j + 4] : s[j]) + r;
        }
        const bool b3 = (lane & 8) != 0;
        float bb[2];
#pragma unroll
        for (int j = 0; j < 2; j++) {
            const float sel = b3 ? a[j] : a[j + 2];
            const float r = __shfl_xor_sync(FULL, sel, 8);
            bb[j] = (b3 ? a[j + 2] : a[j]) + r;
        }
        const bool b2 = (lane & 4) != 0;
        {
            const float sel = b2 ? bb[0] : bb[1];
            const float r = __shfl_xor_sync(FULL, sel, 4);
            float c = (b2 ? bb[1] : bb[0]) + r;
            c += __shfl_xor_sync(FULL, c, 2);
            c += __shfl_xor_sync(FULL, c, 1);
            own_p[g] = c * 0.0625f;
        }
    }

    bool mv;
    {
        int mode = g_mask_mode;
        if (mode == 0)      mv = reinterpret_cast<const float*>(maskp)[t] != 0.0f;
        else if (mode == 1) mv = reinterpret_cast<const int*>(maskp)[t] != 0;
        else                mv = reinterpret_cast<const unsigned char*>(maskp)[t] != 0;
    }
    {
        float mx = -3.4e38f;
#pragma unroll
        for (int g = 0; g < 8; g++) {
            own_p[g] = mv ? own_p[g] : -1.0e9f;
            mx = fmaxf(mx, own_p[g]);
        }
        float sum = 0.f;
#pragma unroll
        for (int g = 0; g < 8; g++) { own_p[g] = expf(own_p[g] - mx); sum += own_p[g]; }
        const float inv = 1.0f / sum;
#pragma unroll
        for (int g = 0; g < 8; g++) own_p[g] *= inv;
    }

    float4 x0[8], x1[8];
#pragma unroll
    for (int h = 0; h < 8; h++) {
        x0[h] = make_float4(0.f, 0.f, 0.f, 0.f);
        x1[h] = make_float4(0.f, 0.f, 0.f, 0.f);
    }
#pragma unroll
    for (int g = 0; g < 8; g++) {
        const float4 v0 = vb[g * 64 + lane * 2];
        const float4 v1 = vb[g * 64 + lane * 2 + 1];
#pragma unroll
        for (int h = 0; h < 8; h++) {
            const float pg = __shfl_sync(FULL, own_p[g], h << 2);
            x0[h].x += pg * v0.x; x0[h].y += pg * v0.y;
            x0[h].z += pg * v0.z; x0[h].w += pg * v0.w;
            x1[h].x += pg * v1.x; x1[h].y += pg * v1.y;
            x1[h].z += pg * v1.z; x1[h].w += pg * v1.w;
        }
    }

    const int b = t >> 11, sIdx = t & 2047;
    const int kidx = (sIdx & 7) * 256 + lane * 8;
    const int pp = kidx >> 5, c = (kidx & 31) >> 3;
#pragma unroll
    for (int h = 0; h < 8; h++) {
        const int ar = b * 2048 + h * 256 + (sIdx >> 3);
        char* base = reinterpret_cast<char*>(g_AX) + (((size_t)pp * NTOK + ar) << 7);
        bf16 b0[8], b1[8];
        split2(x0[h].x, b0[0], b1[0]); split2(x0[h].y, b0[1], b1[1]);
        split2(x0[h].z, b0[2], b1[2]); split2(x0[h].w, b0[3], b1[3]);
        split2(x1[h].x, b0[4], b1[4]); split2(x1[h].y, b0[5], b1[5]);
        split2(x1[h].z, b0[6], b1[6]); split2(x1[h].w, b0[7], b1[7]);
        *reinterpret_cast<uint4*>(base + ((c ^ (ar & 7)) << 4)) =
            *reinterpret_cast<uint4*>(b0);
        *reinterpret_cast<uint4*>(base + (((c + 4) ^ (ar & 7)) << 4)) =
            *reinterpret_cast<uint4*>(b1);
    }
}

// ---------------- launch ------------------------------------------------------
extern "C" void kernel_launch(void* const* d_in, const int* in_sizes, int n_in,
                              void* d_out, int out_size) {
    const float* query = (const float*)d_in[0];
    const float* key   = (const float*)d_in[1];
    const float* value = (const float*)d_in[2];
    const void*  mask  = d_in[3];
    const float* Wq = (const float*)d_in[4];
    const float* bq = (const float*)d_in[5];
    const float* Wk = (const float*)d_in[6];
    const float* bk = (const float*)d_in[7];
    const float* Wv = (const float*)d_in[8];
    const float* bv = (const float*)d_in[9];
    const float* Wo = (const float*)d_in[10];
    const float* bo = (const float*)d_in[11];
    float* out = (float*)d_out;

    cudaFuncSetAttribute(gemm_ps<256, 3>,
                         cudaFuncAttributeMaxDynamicSharedMemorySize, GEMM_SMEM);
    cudaFuncSetAttribute(gemm_ps<128, 4>,
                         cudaFuncAttributeMaxDynamicSharedMemorySize, GEMM_SMEM);

    split_inputs<<<dim3((NTOK * DMODEL / 4) / 256, 3), 256>>>(
        (const float4*)query, (const float4*)key, (const float4*)value,
        (const unsigned char*)mask);
    wsplit<<<dim3(64, 64, 4), dim3(32, 8)>>>(Wq, Wk, Wv, Wo);

    bf16 *Aq, *Ak, *Av, *AX, *Bq, *Bk, *Bv, *Bo;
    float *Qp, *Kp, *Vp;
    cudaGetSymbolAddress((void**)&Aq, g_Aq);
    cudaGetSymbolAddress((void**)&Ak, g_Ak);
    cudaGetSymbolAddress((void**)&Av, g_Av);
    cudaGetSymbolAddress((void**)&AX, g_AX);
    cudaGetSymbolAddress((void**)&Bq, g_Bq);
    cudaGetSymbolAddress((void**)&Bk, g_Bk);
    cudaGetSymbolAddress((void**)&Bv, g_Bv);
    cudaGetSymbolAddress((void**)&Bo, g_Bo);
    cudaGetSymbolAddress((void**)&Qp, g_Q);
    cudaGetSymbolAddress((void**)&Kp, g_Kp);
    cudaGetSymbolAddress((void**)&Vp, g_Vp);

    // merged Q/K/V projections: M=256 tiles, grid (8, 64, 3)
    GemmArgs3 qkv;
    qkv.g[0] = { Aq, Bq, bq, Qp };
    qkv.g[1] = { Ak, Bk, bk, Kp };
    qkv.g[2] = { Av, Bv, bv, Vp };
    gemm_ps<256, 3><<<dim3(DHID / 256, NTOK / 256, 3), 256, GEMM_SMEM>>>(
        qkv, DMODEL, DHID);

    // warp-per-token attention: 12 warps/CTA
    attn_warp<<<(NTOK + 11) / 12, 384>>>(mask);

    // output projection: M=128 tiles, grid (1, 128)   [round-13 config]
    GemmArgs3 oarg;
    oarg.g[0] = { AX, Bo, bo, out };
    oarg.g[1] = oarg.g[0];
    oarg.g[2] = oarg.g[0];
    gemm_ps<128, 4><<<dim3(DMODEL / 256, NTOK / 128, 1), 256, GEMM_SMEM>>>(
        oarg, DHID, DMODEL);
}